// round 6
// baseline (speedup 1.0000x reference)
#include <cuda_runtime.h>

// WideComponent: out[b] = emb_user[u[b]] + emb_item[i[b]] + emb_cat[c[b]]
//                       + cross_w[u[b]*D_CAT + c[b]]
//                       + cross_w[OFF_IC + i[b]*D_CAT + c[b]]
// D_USER=100000, D_ITEM=50000, D_CAT=1000, OFF_IC = 100,000,000. B = 16384.
//
// Final: measured co-best configuration (R2). Wall-clock is pinned at the
// graph-replay floor (~6.6us across 5 kernel shapes); this layout has the
// best measured warm wall time AND best cold device time:
//   128 CTAs x 128 threads -> 512 warps across ~all 148 SMs, single wave,
//   5 independent gathers front-batched per thread (MLP=5), 21 regs.

static constexpr int D_CAT  = 1000;
static constexpr int OFF_IC = 100000 * D_CAT;  // 100,000,000

__global__ void __launch_bounds__(128) wide_kernel(
    const int* __restrict__ user_id,
    const int* __restrict__ item_id,
    const int* __restrict__ category,
    const float* __restrict__ emb_user,
    const float* __restrict__ emb_item,
    const float* __restrict__ emb_cat,
    const float* __restrict__ cross_w,
    float* __restrict__ out,
    int n)
{
    int b = blockIdx.x * blockDim.x + threadIdx.x;
    if (b >= n) return;

    // Three independent index loads (coalesced, L2-hot across replays)
    int u = __ldg(&user_id[b]);
    int i = __ldg(&item_id[b]);
    int c = __ldg(&category[b]);

    // Five independent gathers, front-batched by ptxas (MLP=5).
    float wu = __ldg(&emb_user[u]);
    float wi = __ldg(&emb_item[i]);
    float wc = __ldg(&emb_cat[c]);
    float xu = __ldg(&cross_w[u * D_CAT + c]);
    float xi = __ldg(&cross_w[OFF_IC + i * D_CAT + c]);

    out[b] = wu + wi + wc + xu + xi;
}

extern "C" void kernel_launch(void* const* d_in, const int* in_sizes, int n_in,
                              void* d_out, int out_size)
{
    const int*   user_id  = (const int*)  d_in[0];
    const int*   item_id  = (const int*)  d_in[1];
    const int*   category = (const int*)  d_in[2];
    const float* emb_user = (const float*)d_in[3];
    const float* emb_item = (const float*)d_in[4];
    const float* emb_cat  = (const float*)d_in[5];
    const float* cross_w  = (const float*)d_in[6];
    float*       out      = (float*)d_out;

    int n = in_sizes[0];  // B = 16384
    int threads = 128;    // 128 CTAs -> near-full SM coverage, single wave
    int blocks = (n + threads - 1) / threads;
    wide_kernel<<<blocks, threads>>>(user_id, item_id, category,
                                     emb_user, emb_item, emb_cat, cross_w,
                                     out, n);
}

// round 9
// speedup vs baseline: 1.0435x; 1.0435x over previous
#include <cuda_runtime.h>

// WideComponent: out[b] = emb_user[u[b]] + emb_item[i[b]] + emb_cat[c[b]]
//                       + cross_w[u[b]*D_CAT + c[b]]
//                       + cross_w[OFF_IC + i[b]*D_CAT + c[b]]
// D_USER=100000, D_ITEM=50000, D_CAT=1000, OFF_IC = 100,000,000. B = 16384.
//
// FINAL (resubmit after R6 container-infra failure). Overhead-bound kernel
// at the graph-replay floor: six measured variants (thread geometry,
// vectorization, issue order, predication) all land at 6.7 +/- 0.3 us, and
// an identical-source rerun showed +/-0.3 us run-to-run noise. Warm device
// work is ~0.4us (two dependent L2 hops); the rest is fixed per-replay
// launch latency. Measured-best configuration: 128 CTAs x 128 threads
// (full SM coverage, single wave), 5 independent gathers front-batched per
// thread (MLP=5), 22 regs.

static constexpr int D_CAT  = 1000;
static constexpr int OFF_IC = 100000 * D_CAT;  // 100,000,000

__global__ void __launch_bounds__(128) wide_kernel(
    const int* __restrict__ user_id,
    const int* __restrict__ item_id,
    const int* __restrict__ category,
    const float* __restrict__ emb_user,
    const float* __restrict__ emb_item,
    const float* __restrict__ emb_cat,
    const float* __restrict__ cross_w,
    float* __restrict__ out,
    int n)
{
    int b = blockIdx.x * blockDim.x + threadIdx.x;
    if (b >= n) return;

    // Three independent index loads (coalesced, L2-hot across replays)
    int u = __ldg(&user_id[b]);
    int i = __ldg(&item_id[b]);
    int c = __ldg(&category[b]);

    // Five independent gathers, front-batched by ptxas (MLP=5).
    float wu = __ldg(&emb_user[u]);
    float wi = __ldg(&emb_item[i]);
    float wc = __ldg(&emb_cat[c]);
    float xu = __ldg(&cross_w[u * D_CAT + c]);
    float xi = __ldg(&cross_w[OFF_IC + i * D_CAT + c]);

    out[b] = wu + wi + wc + xu + xi;
}

extern "C" void kernel_launch(void* const* d_in, const int* in_sizes, int n_in,
                              void* d_out, int out_size)
{
    const int*   user_id  = (const int*)  d_in[0];
    const int*   item_id  = (const int*)  d_in[1];
    const int*   category = (const int*)  d_in[2];
    const float* emb_user = (const float*)d_in[3];
    const float* emb_item = (const float*)d_in[4];
    const float* emb_cat  = (const float*)d_in[5];
    const float* cross_w  = (const float*)d_in[6];
    float*       out      = (float*)d_out;

    int n = in_sizes[0];  // B = 16384
    int threads = 128;    // 128 CTAs -> near-full SM coverage, single wave
    int blocks = (n + threads - 1) / threads;
    wide_kernel<<<blocks, threads>>>(user_id, item_id, category,
                                     emb_user, emb_item, emb_cat, cross_w,
                                     out, n);
}